// round 9
// baseline (speedup 1.0000x reference)
#include <cuda_runtime.h>
#include <math.h>
#include <limits.h>

#define EPSV 1e-12f
#define DIMS 768
#define MAXM (131072)
#define KMAX 8
#define NBLK_T 148               // >=148: dodge low-grid issue throttle; single wave
#define TPB 256
#define WPB (TPB / 32)

// Scratch (no cudaMalloc allowed)
__device__ float g_scores[MAXM];
__device__ float g_cand_val[NBLK_T * KMAX];
__device__ int   g_cand_idx[NBLK_T * KMAX];
__device__ unsigned int g_done = 0;   // last-block-done counter (reset each run)

// Ordering consistent with jax.lax.top_k: higher value first, lower index on ties.
__device__ __forceinline__ bool better(float v1, int i1, float v2, int i2) {
    return (v1 > v2) || (v1 == v2 && i1 < i2);
}

// Branchless sorted-insert into a register-resident descending top-K list.
// All indices compile-time -> stays in registers (no LDL/STL).
template<int K>
__device__ __forceinline__ void insertK(float (&lv)[K], int (&li)[K], float v, int i) {
    if (!better(v, i, lv[K - 1], li[K - 1])) return;
    bool b[K];
    #pragma unroll
    for (int j = 0; j < K; j++) b[j] = better(lv[j], li[j], v, i);
    #pragma unroll
    for (int j = K - 1; j >= 1; --j) {
        lv[j] = b[j] ? lv[j] : (b[j - 1] ? v : lv[j - 1]);
        li[j] = b[j] ? li[j] : (b[j - 1] ? i : li[j - 1]);
    }
    if (!b[0]) { lv[0] = v; li[0] = i; }
}

// Full-warp merge: after this, EVERY lane holds the warp's merged top-K.
// 5 shfl rounds, no barriers, no shared memory.
template<int K>
__device__ __forceinline__ void warpMergeK(float (&lv)[K], int (&li)[K]) {
    #pragma unroll
    for (int o = 16; o; o >>= 1) {
        float pv[K];
        int   pi[K];
        #pragma unroll
        for (int j = 0; j < K; j++) {
            pv[j] = __shfl_xor_sync(0xffffffffu, lv[j], o);
            pi[j] = __shfl_xor_sync(0xffffffffu, li[j], o);
        }
        #pragma unroll
        for (int j = 0; j < K; j++) insertK<K>(lv, li, pv[j], pi[j]);
    }
}

// ---------------------------------------------------------------------------
// Kernel 1: fused scoring, one warp per memory row. Barrier-free (proven).
// ---------------------------------------------------------------------------
__global__ void __launch_bounds__(TPB)
score_kernel(const float4* __restrict__ q4,
             const float*  __restrict__ loc,
             const float4* __restrict__ feats4,
             const float2* __restrict__ locs2,
             const float4* __restrict__ meta4,
             int M)
{
    const int wid  = threadIdx.x >> 5;
    const int lane = threadIdx.x & 31;
    const int row  = blockIdx.x * (TPB / 32) + wid;
    if (row >= M) return;

    float2 lrow = make_float2(0.f, 0.f);
    float4 mrow = make_float4(0.f, 0.f, 0.f, 0.f);
    float  l0 = 0.f, l1 = 0.f;
    if (lane == 0) {
        lrow = __ldg(locs2 + row);
        mrow = __ldg(meta4 + row);
        l0 = __ldg(loc);
        l1 = __ldg(loc + 1);
    }

    const float4* __restrict__ rp = feats4 + (size_t)row * (DIMS / 4);

    float4 a0 = __ldcs(rp + lane + 32 * 0);
    float4 a1 = __ldcs(rp + lane + 32 * 1);
    float4 a2 = __ldcs(rp + lane + 32 * 2);
    float4 a3 = __ldcs(rp + lane + 32 * 3);
    float4 a4 = __ldcs(rp + lane + 32 * 4);
    float4 a5 = __ldcs(rp + lane + 32 * 5);

    float dot = 0.f, ss = 0.f, qq = 0.f;
    {
        float4 b;
        b = __ldg(q4 + lane + 32 * 0);
        dot += a0.x*b.x + a0.y*b.y + a0.z*b.z + a0.w*b.w;
        ss  += a0.x*a0.x + a0.y*a0.y + a0.z*a0.z + a0.w*a0.w;
        qq  += b.x*b.x + b.y*b.y + b.z*b.z + b.w*b.w;
        b = __ldg(q4 + lane + 32 * 1);
        dot += a1.x*b.x + a1.y*b.y + a1.z*b.z + a1.w*b.w;
        ss  += a1.x*a1.x + a1.y*a1.y + a1.z*a1.z + a1.w*a1.w;
        qq  += b.x*b.x + b.y*b.y + b.z*b.z + b.w*b.w;
        b = __ldg(q4 + lane + 32 * 2);
        dot += a2.x*b.x + a2.y*b.y + a2.z*b.z + a2.w*b.w;
        ss  += a2.x*a2.x + a2.y*a2.y + a2.z*a2.z + a2.w*a2.w;
        qq  += b.x*b.x + b.y*b.y + b.z*b.z + b.w*b.w;
        b = __ldg(q4 + lane + 32 * 3);
        dot += a3.x*b.x + a3.y*b.y + a3.z*b.z + a3.w*b.w;
        ss  += a3.x*a3.x + a3.y*a3.y + a3.z*a3.z + a3.w*a3.w;
        qq  += b.x*b.x + b.y*b.y + b.z*b.z + b.w*b.w;
        b = __ldg(q4 + lane + 32 * 4);
        dot += a4.x*b.x + a4.y*b.y + a4.z*b.z + a4.w*b.w;
        ss  += a4.x*a4.x + a4.y*a4.y + a4.z*a4.z + a4.w*a4.w;
        qq  += b.x*b.x + b.y*b.y + b.z*b.z + b.w*b.w;
        b = __ldg(q4 + lane + 32 * 5);
        dot += a5.x*b.x + a5.y*b.y + a5.z*b.z + a5.w*b.w;
        ss  += a5.x*a5.x + a5.y*a5.y + a5.z*a5.z + a5.w*a5.w;
        qq  += b.x*b.x + b.y*b.y + b.z*b.z + b.w*b.w;
    }

    #pragma unroll
    for (int o = 16; o; o >>= 1) {
        dot += __shfl_xor_sync(0xffffffffu, dot, o);
        ss  += __shfl_xor_sync(0xffffffffu, ss,  o);
        qq  += __shfl_xor_sync(0xffffffffu, qq,  o);
    }

    if (lane == 0) {
        float qn = fmaxf(sqrtf(qq), EPSV);
        float mn = fmaxf(sqrtf(ss), EPSV);
        float sim = dot / (mn * qn);

        float dx = lrow.x - l0;
        float dy = lrow.y - l1;
        float spatial = 1.f / (1.f + sqrtf(dx * dx + dy * dy));

        // exp(-(3600 - ts)/3600) == exp(ts/3600 - 1)
        float temporal = expf(mrow.y * (1.f / 3600.f) - 1.f);

        g_scores[row] = (0.5f * sim + 0.3f * spatial + 0.2f * temporal) * mrow.x;
    }
}

// ---------------------------------------------------------------------------
// Kernel 2: single-launch top-k via register-list merges (no selection passes).
// ---------------------------------------------------------------------------
template<int K>
__global__ void __launch_bounds__(TPB)
topk_tail(int M, float* __restrict__ out)
{
    __shared__ float s_wval[WPB * K];
    __shared__ int   s_widx[WPB * K];
    __shared__ bool  s_last;

    const int wid  = threadIdx.x >> 5;
    const int lane = threadIdx.x & 31;

    // ---- phase 1: per-thread register top-K over grid-stride float4 slice ----
    float lv[K];
    int   li[K];
    #pragma unroll
    for (int j = 0; j < K; j++) { lv[j] = -INFINITY; li[j] = INT_MAX; }

    const float4* sc4 = (const float4*)g_scores;
    const int n4 = M >> 2;
    for (int i = blockIdx.x * TPB + threadIdx.x; i < n4; i += NBLK_T * TPB) {
        float4 v = sc4[i];
        const int base = 4 * i;
        insertK<K>(lv, li, v.x, base + 0);
        insertK<K>(lv, li, v.y, base + 1);
        insertK<K>(lv, li, v.z, base + 2);
        insertK<K>(lv, li, v.w, base + 3);
    }
    if (blockIdx.x == 0) {                     // M % 4 remainder
        int i = (n4 << 2) + threadIdx.x;
        if (i < M) insertK<K>(lv, li, g_scores[i], i);
    }

    // ---- phase 2: warp merge (shfl) -> cross-warp merge (shared + shfl) ----
    warpMergeK<K>(lv, li);
    if (lane == 0) {
        #pragma unroll
        for (int j = 0; j < K; j++) {
            s_wval[wid * K + j] = lv[j];
            s_widx[wid * K + j] = li[j];
        }
    }
    __syncthreads();

    if (wid == 0) {
        float mv[K];
        int   mi[K];
        #pragma unroll
        for (int j = 0; j < K; j++) { mv[j] = -INFINITY; mi[j] = INT_MAX; }
        if (lane < WPB) {
            #pragma unroll
            for (int j = 0; j < K; j++) { mv[j] = s_wval[lane * K + j]; mi[j] = s_widx[lane * K + j]; }
        }
        warpMergeK<K>(mv, mi);
        // thread 0 owns the block result: write, fence, arrive (single-thread order)
        if (lane == 0) {
            #pragma unroll
            for (int j = 0; j < K; j++) {
                g_cand_val[blockIdx.x * K + j] = mv[j];
                g_cand_idx[blockIdx.x * K + j] = mi[j];
            }
            __threadfence();
            unsigned int t = atomicAdd(&g_done, 1u);
            s_last = (t == (unsigned int)(NBLK_T - 1));
        }
    }
    __syncthreads();
    if (!s_last) return;
    __threadfence();

    // ---- phase 3: last block merges all candidates (148*K <= 1184) ----
    const int ncand = NBLK_T * K;
    #pragma unroll
    for (int j = 0; j < K; j++) { lv[j] = -INFINITY; li[j] = INT_MAX; }
    for (int p = threadIdx.x; p < ncand; p += TPB)
        insertK<K>(lv, li, __ldcg(&g_cand_val[p]), __ldcg(&g_cand_idx[p]));

    warpMergeK<K>(lv, li);
    if (lane == 0) {
        #pragma unroll
        for (int j = 0; j < K; j++) {
            s_wval[wid * K + j] = lv[j];
            s_widx[wid * K + j] = li[j];
        }
    }
    __syncthreads();

    if (wid == 0) {
        float mv[K];
        int   mi[K];
        #pragma unroll
        for (int j = 0; j < K; j++) { mv[j] = -INFINITY; mi[j] = INT_MAX; }
        if (lane < WPB) {
            #pragma unroll
            for (int j = 0; j < K; j++) { mv[j] = s_wval[lane * K + j]; mi[j] = s_widx[lane * K + j]; }
        }
        warpMergeK<K>(mv, mi);
        if (lane == 0) {
            #pragma unroll
            for (int j = 0; j < K; j++) {
                out[j]     = mv[j];          // top_scores (sorted desc, ties by index)
                out[K + j] = (float)mi[j];   // top_indices (exact in fp32 for idx < 2^24)
            }
            g_done = 0;                      // reset for next graph replay
        }
    }
}

// ---------------------------------------------------------------------------
// Launch
// ---------------------------------------------------------------------------
extern "C" void kernel_launch(void* const* d_in, const int* in_sizes, int n_in,
                              void* d_out, int out_size)
{
    const float* q     = (const float*)d_in[0];   // (768,)
    const float* loc   = (const float*)d_in[1];   // (2,)
    const float* feats = (const float*)d_in[2];   // (M, 768)
    const float* locs  = (const float*)d_in[3];   // (M, 2)
    const float* meta  = (const float*)d_in[4];   // (M, 4)
    float* out = (float*)d_out;                   // [k scores | k indices]

    int M = in_sizes[2] / DIMS;
    if (M > MAXM) M = MAXM;
    int k = out_size / 2;
    if (k < 1) k = 1;
    if (k > KMAX) k = KMAX;

    const int warps_per_block = TPB / 32;
    const int nblk_score = (M + warps_per_block - 1) / warps_per_block;

    score_kernel<<<nblk_score, TPB>>>((const float4*)q, loc,
                                      (const float4*)feats,
                                      (const float2*)locs,
                                      (const float4*)meta, M);

    switch (k) {
        case 1: topk_tail<1><<<NBLK_T, TPB>>>(M, out); break;
        case 2: topk_tail<2><<<NBLK_T, TPB>>>(M, out); break;
        case 3: topk_tail<3><<<NBLK_T, TPB>>>(M, out); break;
        case 4: topk_tail<4><<<NBLK_T, TPB>>>(M, out); break;
        case 5: topk_tail<5><<<NBLK_T, TPB>>>(M, out); break;
        case 6: topk_tail<6><<<NBLK_T, TPB>>>(M, out); break;
        case 7: topk_tail<7><<<NBLK_T, TPB>>>(M, out); break;
        default: topk_tail<8><<<NBLK_T, TPB>>>(M, out); break;
    }
}